// round 2
// baseline (speedup 1.0000x reference)
#include <cuda_runtime.h>
#include <math.h>

#define BB 16
#define NN 2048
#define MM 2048
#define TPB 256
#define RPB 32
#define PARTS (NN / RPB)      /* 64  */
#define PRO_RPB 16
#define SKIP_T (-57.5f)       /* log2 threshold: maxe*2048 < 1e-14 */

/* ---- scratch: __device__ globals (no runtime allocation) ---- */
__device__ float g_d2[(size_t)BB * NN * MM];    /* 268 MB */
__device__ float g_dist[(size_t)BB * NN * MM];  /* 268 MB */
__device__ float g_rowmin[BB * NN];
__device__ float g_rl[BB * NN];
__device__ float g_rlors[BB * NN];
__device__ float g_cost[BB * NN];
__device__ float g_rr[BB * MM];
__device__ float g_q[BB * MM];
__device__ float g_part[(size_t)BB * PARTS * MM];
__device__ float g_S[BB];
__device__ float g_RLOR[BB];

__global__ void __launch_bounds__(TPB) k_init() {
    int i = blockIdx.x * TPB + threadIdx.x;
    if (i < BB * NN) { g_rl[i] = 1.0f; g_cost[i] = 0.0f; }
    if (i < BB * MM) g_rr[i] = 1.0f;  /* n==m -> factorl=factorr=1 */
}

/* Prologue: d2 = |x1-x2|^2, dist = sqrt(max(d2,1e-12)), per-row min d2. */
__global__ void __launch_bounds__(TPB) k_prologue(const float* __restrict__ xyz1,
                                                  const float* __restrict__ xyz2) {
    __shared__ __align__(16) float sx[MM];
    __shared__ __align__(16) float sy[MM];
    __shared__ __align__(16) float sz[MM];
    __shared__ float s_red[2][8];
    const int tid = threadIdx.x;
    const int b = blockIdx.y;
    const int bx = blockIdx.x;

    const float* p2 = xyz2 + (size_t)b * MM * 3;
    for (int lin = tid; lin < MM * 3; lin += TPB) {
        float v = p2[lin];
        int pt = lin / 3, cmp = lin - 3 * pt;
        if (cmp == 0) sx[pt] = v; else if (cmp == 1) sy[pt] = v; else sz[pt] = v;
    }
    __syncthreads();

    float4* D2 = (float4*)g_d2;
    float4* DS = (float4*)g_dist;

    for (int r = 0; r < PRO_RPB; r++) {
        int row = bx * PRO_RPB + r;
        int gi = b * NN + row;
        float x1 = xyz1[(size_t)gi * 3 + 0];
        float y1 = xyz1[(size_t)gi * 3 + 1];
        float z1 = xyz1[(size_t)gi * 3 + 2];
        size_t rb = ((size_t)gi * MM) >> 2;
        float m = 3.4e38f;
#pragma unroll
        for (int c = 0; c < 2; c++) {
            int ji = c * 256 + tid;
            float4 X = ((const float4*)sx)[ji];
            float4 Y = ((const float4*)sy)[ji];
            float4 Z = ((const float4*)sz)[ji];
            float4 d2v, dsv;
            float dx, dy, dz;
            dx = x1 - X.x; dy = y1 - Y.x; dz = z1 - Z.x; d2v.x = dx*dx + dy*dy + dz*dz;
            dx = x1 - X.y; dy = y1 - Y.y; dz = z1 - Z.y; d2v.y = dx*dx + dy*dy + dz*dz;
            dx = x1 - X.z; dy = y1 - Y.z; dz = z1 - Z.z; d2v.z = dx*dx + dy*dy + dz*dz;
            dx = x1 - X.w; dy = y1 - Y.w; dz = z1 - Z.w; d2v.w = dx*dx + dy*dy + dz*dz;
            m = fminf(m, fminf(fminf(d2v.x, d2v.y), fminf(d2v.z, d2v.w)));
            dsv.x = sqrtf(fmaxf(d2v.x, 1e-12f));
            dsv.y = sqrtf(fmaxf(d2v.y, 1e-12f));
            dsv.z = sqrtf(fmaxf(d2v.z, 1e-12f));
            dsv.w = sqrtf(fmaxf(d2v.w, 1e-12f));
            D2[rb + ji] = d2v;
            DS[rb + ji] = dsv;
        }
#pragma unroll
        for (int o = 16; o > 0; o >>= 1)
            m = fminf(m, __shfl_xor_sync(0xffffffffu, m, o));
        float* red = s_red[r & 1];
        if ((tid & 31) == 0) red[tid >> 5] = m;
        __syncthreads();
        if (tid == 0) {
            float mm = red[0];
#pragma unroll
            for (int k = 1; k < 8; k++) mm = fminf(mm, red[k]);
            g_rowmin[gi] = mm;
        }
    }
}

__device__ __forceinline__ float4 exp2f4(float c, float4 a) {
    float4 r;
    r.x = exp2f(c * a.x); r.y = exp2f(c * a.y);
    r.z = exp2f(c * a.z); r.w = exp2f(c * a.w);
    return r;
}
__device__ __forceinline__ float4 pow4f4(float4 e) {
    float4 r;
    float t;
    t = e.x * e.x; r.x = t * t;
    t = e.y * e.y; r.y = t * t;
    t = e.z * e.z; r.z = t * t;
    t = e.w * e.w; r.w = t * t;
    return r;
}

/* Fused round kernel.
 * A-side (doA): e_A = exp2(cA*d2); rowsum = sum e_A*rr; rlors = rl/(rowsum+1e-9);
 *               column partials tacc_j += e_A*rlors.
 * C-side (doC): e_C = e_A^4 (previous round's e); uses stored rlors_prev and q:
 *               cost += rlors_prev * sum(e_C*q*dist); rl = max(rl - rlors_prev*sum(e_C*q), 0).
 * cA == 0 means e == 1 (level-0 dist-only pass; skips d2 load). */
__global__ void __launch_bounds__(TPB) k_round(float cA, int doC, int doA) {
    __shared__ __align__(16) float4 s_rr[MM / 4];
    __shared__ __align__(16) float4 s_q[MM / 4];
    __shared__ float s_redbuf[48];
    const int tid = threadIdx.x;
    const int b = blockIdx.y;
    const int bx = blockIdx.x;

    if (doA) {
        const float4* R = (const float4*)(g_rr + (size_t)b * MM);
        s_rr[tid] = R[tid];
        s_rr[256 + tid] = R[256 + tid];
    }
    if (doC) {
        const float4* Q = (const float4*)(g_q + (size_t)b * MM);
        s_q[tid] = Q[tid];
        s_q[256 + tid] = Q[256 + tid];
    }
    __syncthreads();

    float4 t0 = make_float4(0.f, 0.f, 0.f, 0.f);
    float4 t1 = make_float4(0.f, 0.f, 0.f, 0.f);
    const float4* D2 = (const float4*)g_d2;
    const float4* DS = (const float4*)g_dist;
    int pr = 0;

    for (int r = 0; r < RPB; r++) {
        int row = bx * RPB + r;
        int gi = b * NN + row;
        float rlors_prev = doC ? g_rlors[gi] : 0.0f;
        bool actC = doC && (rlors_prev != 0.0f);
        bool actA = doA && (cA * g_rowmin[gi] >= SKIP_T);
        if (!actA && !actC) {
            if (doA && tid == 0) g_rlors[gi] = 0.0f;
            continue;
        }
        size_t rb = ((size_t)gi * MM) >> 2;
        float4 e0 = make_float4(1.f, 1.f, 1.f, 1.f);
        float4 e1 = make_float4(1.f, 1.f, 1.f, 1.f);
        if (cA != 0.0f) {
            float4 a0 = D2[rb + tid];
            float4 a1 = D2[rb + 256 + tid];
            e0 = exp2f4(cA, a0);
            e1 = exp2f4(cA, a1);
        }
        float cacc = 0.f, lacc = 0.f, racc = 0.f;
        if (actC) {
            float4 c0 = pow4f4(e0);
            float4 c1 = pow4f4(e1);
            float4 q0 = s_q[tid], q1 = s_q[256 + tid];
            float4 d0 = DS[rb + tid], d1 = DS[rb + 256 + tid];
            float w;
            w = c0.x * q0.x; cacc += w * d0.x; lacc += w;
            w = c0.y * q0.y; cacc += w * d0.y; lacc += w;
            w = c0.z * q0.z; cacc += w * d0.z; lacc += w;
            w = c0.w * q0.w; cacc += w * d0.w; lacc += w;
            w = c1.x * q1.x; cacc += w * d1.x; lacc += w;
            w = c1.y * q1.y; cacc += w * d1.y; lacc += w;
            w = c1.z * q1.z; cacc += w * d1.z; lacc += w;
            w = c1.w * q1.w; cacc += w * d1.w; lacc += w;
        }
        if (actA) {
            float4 r0 = s_rr[tid], r1 = s_rr[256 + tid];
            racc = e0.x * r0.x + e0.y * r0.y + e0.z * r0.z + e0.w * r0.w
                 + e1.x * r1.x + e1.y * r1.y + e1.z * r1.z + e1.w * r1.w;
        }
        /* block-reduce (cacc, lacc, racc) */
        float va = cacc, vb = lacc, vc = racc;
#pragma unroll
        for (int o = 16; o > 0; o >>= 1) {
            va += __shfl_xor_sync(0xffffffffu, va, o);
            vb += __shfl_xor_sync(0xffffffffu, vb, o);
            vc += __shfl_xor_sync(0xffffffffu, vc, o);
        }
        float* red = s_redbuf + (pr & 1) * 24;
        if ((tid & 31) == 0) {
            int w = tid >> 5;
            red[w] = va; red[8 + w] = vb; red[16 + w] = vc;
        }
        __syncthreads();
        float Rc = 0.f, Rl = 0.f, Rs = 0.f;
#pragma unroll
        for (int k = 0; k < 8; k++) { Rc += red[k]; Rl += red[8 + k]; Rs += red[16 + k]; }
        pr++;

        float rl = g_rl[gi];
        float rl_new = actC ? fmaxf(rl - rlors_prev * Rl, 0.0f) : rl;
        if (tid == 0 && actC) {
            g_cost[gi] += rlors_prev * Rc;
            g_rl[gi] = rl_new;
        }
        if (actA) {
            float rlors_new = rl_new / (Rs + 1e-9f);
            if (tid == 0) g_rlors[gi] = rlors_new;
            t0.x += e0.x * rlors_new; t0.y += e0.y * rlors_new;
            t0.z += e0.z * rlors_new; t0.w += e0.w * rlors_new;
            t1.x += e1.x * rlors_new; t1.y += e1.y * rlors_new;
            t1.z += e1.z * rlors_new; t1.w += e1.w * rlors_new;
        } else if (doA) {
            if (tid == 0) g_rlors[gi] = 0.0f;
        }
    }
    if (doA) {
        float4* P = (float4*)(g_part + ((size_t)b * PARTS + bx) * MM);
        P[tid] = t0;
        P[256 + tid] = t1;
    }
}

/* Column pass: t_j = sum partials; s = min(rr/(rr*t+1e-9),1); q = rr*s; rr -= q*t. */
__global__ void __launch_bounds__(TPB) k_colB() {
    int i = blockIdx.x * TPB + threadIdx.x;
    int b = i / MM, j = i - b * MM;
    const float* P = g_part + (size_t)b * PARTS * MM + j;
    float t = 0.f;
#pragma unroll 8
    for (int p = 0; p < PARTS; p++) t += P[(size_t)p * MM];
    float rr = g_rr[i];
    float ss2 = rr * t;
    float s = fminf(rr / (ss2 + 1e-9f), 1.0f);
    float q = rr * s;
    g_q[i] = q;
    g_rr[i] = fmaxf(rr - q * t, 0.0f);
}

__device__ __forceinline__ float blk_sum(float v, float* red8, int tid) {
#pragma unroll
    for (int o = 16; o > 0; o >>= 1) v += __shfl_xor_sync(0xffffffffu, v, o);
    if ((tid & 31) == 0) red8[tid >> 5] = v;
    __syncthreads();
    float s = 0.f;
#pragma unroll
    for (int k = 0; k < 8; k++) s += red8[k];
    return s;
}

__global__ void __launch_bounds__(TPB) k_S() {
    __shared__ float red[8];
    int b = blockIdx.x, tid = threadIdx.x;
    float s = 0.f;
    for (int j = tid; j < MM; j += TPB) s += g_rr[b * MM + j];
    float S = blk_sum(s, red, tid);
    if (tid == 0) g_S[b] = S;
}

__global__ void __launch_bounds__(TPB) k_rlors0() {
    __shared__ float red[8];
    int b = blockIdx.x, tid = threadIdx.x;
    float S = g_S[b] + 1e-9f;
    float acc = 0.f;
    for (int i = tid; i < NN; i += TPB) {
        float v = g_rl[b * NN + i] / S;
        g_rlors[b * NN + i] = v;
        acc += v;
    }
    float R = blk_sum(acc, red, tid);
    if (tid == 0) g_RLOR[b] = R;
}

__global__ void __launch_bounds__(TPB) k_B0() {
    int i = blockIdx.x * TPB + threadIdx.x;
    int b = i / MM;
    float rr = g_rr[i];
    float ss2 = rr * g_RLOR[b];
    float s = fminf(rr / (ss2 + 1e-9f), 1.0f);
    g_q[i] = rr * s;
}

__global__ void __launch_bounds__(TPB) k_epi(float* __restrict__ out) {
    __shared__ float red[8];
    int b = blockIdx.x, tid = threadIdx.x;
    float acc = 0.f;
    for (int i = tid; i < NN; i += TPB) acc += g_cost[b * NN + i];
    float S = blk_sum(acc, red, tid);
    if (tid == 0) out[b] = S;
}

extern "C" void kernel_launch(void* const* d_in, const int* in_sizes, int n_in,
                              void* d_out, int out_size) {
    const float* xyz1 = (const float*)d_in[0];
    const float* xyz2 = (const float*)d_in[1];
    float* out = (float*)d_out;

    k_init<<<(BB * NN) / TPB, TPB>>>();
    k_prologue<<<dim3(NN / PRO_RPB, BB), TPB>>>(xyz1, xyz2);

    /* c[p] = level_p * log2(e), level_p = -0.25 * 4^p  (p = 8..0) */
    float c[9];
    for (int p = 0; p <= 8; p++)
        c[p] = (float)(-0.25 * pow(4.0, (double)p) * 1.4426950408889634);

    dim3 rg(PARTS, BB);
    /* Round p=8: A only */
    k_round<<<rg, TPB>>>(c[8], 0, 1);
    k_colB<<<(BB * MM) / TPB, TPB>>>();
    /* Fused C(p+1)+A(p) for p=7..0 */
    for (int p = 7; p >= 0; p--) {
        k_round<<<rg, TPB>>>(c[p], 1, 1);
        k_colB<<<(BB * MM) / TPB, TPB>>>();
    }
    /* C(0) standalone: e_C = e_A^4 with cA = c[0]/4 */
    k_round<<<rg, TPB>>>(c[0] * 0.25f, 1, 0);
    /* Level-0 round: separable vector math + dist-only pass */
    k_S<<<BB, TPB>>>();
    k_rlors0<<<BB, TPB>>>();
    k_B0<<<(BB * MM) / TPB, TPB>>>();
    k_round<<<rg, TPB>>>(0.0f, 1, 0);   /* cA==0 -> e==1, reads dist only */

    k_epi<<<BB, TPB>>>(out);
}

// round 3
// speedup vs baseline: 1.2199x; 1.2199x over previous
#include <cuda_runtime.h>
#include <math.h>

#define BB 16
#define NN 2048
#define MM 2048
#define TPB 256
#define RPB 64
#define PARTS (NN / RPB)      /* 32 */
#define PRO_RPB 16
#define SKIP_T (-57.5f)       /* log2 threshold: maxe*2048 << 1e-9 */

/* ---- scratch: __device__ globals (no runtime allocation) ---- */
__device__ float g_d2[(size_t)BB * NN * MM];    /* 268 MB */
__device__ float g_rowmin[BB * NN];
__device__ float g_rl[BB * NN];
__device__ float g_rlors[BB * NN];
__device__ float g_cost[BB * NN];
__device__ float g_D[BB * NN];
__device__ float g_rr[BB * MM];
__device__ float g_q[BB * MM];
__device__ float g_part[(size_t)BB * PARTS * MM];

__global__ void __launch_bounds__(TPB) k_init() {
    int i = blockIdx.x * TPB + threadIdx.x;
    if (i < BB * NN) { g_rl[i] = 1.0f; g_cost[i] = 0.0f; }
    if (i < BB * MM) g_rr[i] = 1.0f;  /* n==m -> factorl=factorr=1 */
}

/* Prologue: d2 = |x1-x2|^2 (268MB write) + per-row min d2 (for skipping). */
__global__ void __launch_bounds__(TPB) k_prologue(const float* __restrict__ xyz1,
                                                  const float* __restrict__ xyz2) {
    __shared__ __align__(16) float sx[MM];
    __shared__ __align__(16) float sy[MM];
    __shared__ __align__(16) float sz[MM];
    __shared__ float s_red[2][8];
    const int tid = threadIdx.x;
    const int b = blockIdx.y;
    const int bx = blockIdx.x;

    const float* p2 = xyz2 + (size_t)b * MM * 3;
    for (int lin = tid; lin < MM * 3; lin += TPB) {
        float v = p2[lin];
        int pt = lin / 3, cmp = lin - 3 * pt;
        if (cmp == 0) sx[pt] = v; else if (cmp == 1) sy[pt] = v; else sz[pt] = v;
    }
    __syncthreads();

    float4* D2 = (float4*)g_d2;

    for (int r = 0; r < PRO_RPB; r++) {
        int row = bx * PRO_RPB + r;
        int gi = b * NN + row;
        float x1 = xyz1[(size_t)gi * 3 + 0];
        float y1 = xyz1[(size_t)gi * 3 + 1];
        float z1 = xyz1[(size_t)gi * 3 + 2];
        size_t rb = ((size_t)gi * MM) >> 2;
        float m = 3.4e38f;
#pragma unroll
        for (int c = 0; c < 2; c++) {
            int ji = c * 256 + tid;
            float4 X = ((const float4*)sx)[ji];
            float4 Y = ((const float4*)sy)[ji];
            float4 Z = ((const float4*)sz)[ji];
            float4 d2v;
            float dx, dy, dz;
            dx = x1 - X.x; dy = y1 - Y.x; dz = z1 - Z.x; d2v.x = dx*dx + dy*dy + dz*dz;
            dx = x1 - X.y; dy = y1 - Y.y; dz = z1 - Z.y; d2v.y = dx*dx + dy*dy + dz*dz;
            dx = x1 - X.z; dy = y1 - Y.z; dz = z1 - Z.z; d2v.z = dx*dx + dy*dy + dz*dz;
            dx = x1 - X.w; dy = y1 - Y.w; dz = z1 - Z.w; d2v.w = dx*dx + dy*dy + dz*dz;
            m = fminf(m, fminf(fminf(d2v.x, d2v.y), fminf(d2v.z, d2v.w)));
            D2[rb + ji] = d2v;
        }
#pragma unroll
        for (int o = 16; o > 0; o >>= 1)
            m = fminf(m, __shfl_xor_sync(0xffffffffu, m, o));
        float* red = s_red[r & 1];
        if ((tid & 31) == 0) red[tid >> 5] = m;
        __syncthreads();
        if (tid == 0) {
            float mm = red[0];
#pragma unroll
            for (int k = 1; k < 8; k++) mm = fminf(mm, red[k]);
            g_rowmin[gi] = mm;
        }
    }
}

__device__ __forceinline__ float4 exp2f4(float c, float4 a) {
    float4 r;
    r.x = exp2f(c * a.x); r.y = exp2f(c * a.y);
    r.z = exp2f(c * a.z); r.w = exp2f(c * a.w);
    return r;
}
__device__ __forceinline__ float4 pow4f4(float4 e) {
    float4 r; float t;
    t = e.x * e.x; r.x = t * t;
    t = e.y * e.y; r.y = t * t;
    t = e.z * e.z; r.z = t * t;
    t = e.w * e.w; r.w = t * t;
    return r;
}
__device__ __forceinline__ float4 sqrt4(float4 a) {
    float4 r;
    r.x = sqrtf(fmaxf(a.x, 1e-12f));
    r.y = sqrtf(fmaxf(a.y, 1e-12f));
    r.z = sqrtf(fmaxf(a.z, 1e-12f));
    r.w = sqrtf(fmaxf(a.w, 1e-12f));
    return r;
}

/* Fused round kernel (cA != 0 always).
 * A-side (doA): e_A = exp2(cA*d2); rowsum = sum e_A*rr; rlors = rl/(rowsum+1e-9);
 *               column partials tacc_j += e_A*rlors.
 * C-side (doC): e_C = e_A^4 (previous round's weights, level 4x); dist = sqrt(d2);
 *               cost += rlors_prev*sum(e_C*q*dist); rl = max(rl - rlors_prev*sum(e_C*q), 0). */
__global__ void __launch_bounds__(TPB) k_round(float cA, int doC, int doA) {
    __shared__ __align__(16) float4 s_rr[MM / 4];
    __shared__ __align__(16) float4 s_q[MM / 4];
    __shared__ float s_redbuf[48];
    const int tid = threadIdx.x;
    const int b = blockIdx.y;
    const int bx = blockIdx.x;

    if (doA) {
        const float4* R = (const float4*)(g_rr + (size_t)b * MM);
        s_rr[tid] = R[tid];
        s_rr[256 + tid] = R[256 + tid];
    }
    if (doC) {
        const float4* Q = (const float4*)(g_q + (size_t)b * MM);
        s_q[tid] = Q[tid];
        s_q[256 + tid] = Q[256 + tid];
    }
    __syncthreads();

    float4 t0 = make_float4(0.f, 0.f, 0.f, 0.f);
    float4 t1 = make_float4(0.f, 0.f, 0.f, 0.f);
    const float4* D2 = (const float4*)g_d2;
    int pr = 0;

    for (int r = 0; r < RPB; r++) {
        int row = bx * RPB + r;
        int gi = b * NN + row;
        float rlors_prev = doC ? g_rlors[gi] : 0.0f;
        bool actC = doC && (rlors_prev != 0.0f);
        bool actA = doA && (cA * g_rowmin[gi] >= SKIP_T);
        if (!actA && !actC) {
            if (doA && tid == 0) g_rlors[gi] = 0.0f;
            continue;
        }
        size_t rb = ((size_t)gi * MM) >> 2;
        float4 a0 = D2[rb + tid];
        float4 a1 = D2[rb + 256 + tid];
        float4 e0 = exp2f4(cA, a0);
        float4 e1 = exp2f4(cA, a1);

        float cacc = 0.f, lacc = 0.f, racc = 0.f;
        if (actC) {
            float4 c0 = pow4f4(e0);
            float4 c1 = pow4f4(e1);
            float4 q0 = s_q[tid], q1 = s_q[256 + tid];
            float4 d0 = sqrt4(a0), d1 = sqrt4(a1);
            float w;
            w = c0.x * q0.x; cacc += w * d0.x; lacc += w;
            w = c0.y * q0.y; cacc += w * d0.y; lacc += w;
            w = c0.z * q0.z; cacc += w * d0.z; lacc += w;
            w = c0.w * q0.w; cacc += w * d0.w; lacc += w;
            w = c1.x * q1.x; cacc += w * d1.x; lacc += w;
            w = c1.y * q1.y; cacc += w * d1.y; lacc += w;
            w = c1.z * q1.z; cacc += w * d1.z; lacc += w;
            w = c1.w * q1.w; cacc += w * d1.w; lacc += w;
        }
        if (actA) {
            float4 r0 = s_rr[tid], r1 = s_rr[256 + tid];
            racc = e0.x * r0.x + e0.y * r0.y + e0.z * r0.z + e0.w * r0.w
                 + e1.x * r1.x + e1.y * r1.y + e1.z * r1.z + e1.w * r1.w;
        }
        /* block-reduce (cacc, lacc, racc) */
        float va = cacc, vb = lacc, vc = racc;
#pragma unroll
        for (int o = 16; o > 0; o >>= 1) {
            va += __shfl_xor_sync(0xffffffffu, va, o);
            vb += __shfl_xor_sync(0xffffffffu, vb, o);
            vc += __shfl_xor_sync(0xffffffffu, vc, o);
        }
        float* red = s_redbuf + (pr & 1) * 24;
        if ((tid & 31) == 0) {
            int w = tid >> 5;
            red[w] = va; red[8 + w] = vb; red[16 + w] = vc;
        }
        __syncthreads();
        float Rc = 0.f, Rl = 0.f, Rs = 0.f;
#pragma unroll
        for (int k = 0; k < 8; k++) { Rc += red[k]; Rl += red[8 + k]; Rs += red[16 + k]; }
        pr++;

        float rl = g_rl[gi];
        float rl_new = actC ? fmaxf(rl - rlors_prev * Rl, 0.0f) : rl;
        if (tid == 0 && actC) {
            g_cost[gi] += rlors_prev * Rc;
            g_rl[gi] = rl_new;
        }
        if (actA) {
            float rlors_new = rl_new / (Rs + 1e-9f);
            if (tid == 0) g_rlors[gi] = rlors_new;
            t0.x += e0.x * rlors_new; t0.y += e0.y * rlors_new;
            t0.z += e0.z * rlors_new; t0.w += e0.w * rlors_new;
            t1.x += e1.x * rlors_new; t1.y += e1.y * rlors_new;
            t1.z += e1.z * rlors_new; t1.w += e1.w * rlors_new;
        } else if (doA) {
            if (tid == 0) g_rlors[gi] = 0.0f;
        }
    }
    if (doA) {
        float4* P = (float4*)(g_part + ((size_t)b * PARTS + bx) * MM);
        P[tid] = t0;
        P[256 + tid] = t1;
    }
}

/* Column pass: t_j = sum partials; s = min(rr/(rr*t+1e-9),1); q = rr*s; rr -= q*t. */
__global__ void __launch_bounds__(TPB) k_colB() {
    int i = blockIdx.x * TPB + threadIdx.x;
    int b = i / MM, j = i - b * MM;
    const float* P = g_part + (size_t)b * PARTS * MM + j;
    float t = 0.f;
#pragma unroll 8
    for (int p = 0; p < PARTS; p++) t += P[(size_t)p * MM];
    float rr = g_rr[i];
    float ss2 = rr * t;
    float s = fminf(rr / (ss2 + 1e-9f), 1.0f);
    float q = rr * s;
    g_q[i] = q;
    g_rr[i] = fmaxf(rr - q * t, 0.0f);
}

/* Final pass: C-side of round p=0 (e = exp2(c0*d2)) fused with the level-0
 * row sums D_i = sum_j rr_j * dist_ij. */
__global__ void __launch_bounds__(TPB) k_final(float c0) {
    __shared__ __align__(16) float4 s_rr[MM / 4];
    __shared__ __align__(16) float4 s_q[MM / 4];
    __shared__ float s_redbuf[48];
    const int tid = threadIdx.x;
    const int b = blockIdx.y;
    const int bx = blockIdx.x;

    {
        const float4* R = (const float4*)(g_rr + (size_t)b * MM);
        const float4* Q = (const float4*)(g_q + (size_t)b * MM);
        s_rr[tid] = R[tid];  s_rr[256 + tid] = R[256 + tid];
        s_q[tid]  = Q[tid];  s_q[256 + tid]  = Q[256 + tid];
    }
    __syncthreads();

    const float4* D2 = (const float4*)g_d2;
    int pr = 0;

    for (int r = 0; r < RPB; r++) {
        int row = bx * RPB + r;
        int gi = b * NN + row;
        float rlors_prev = g_rlors[gi];
        size_t rb = ((size_t)gi * MM) >> 2;
        float4 a0 = D2[rb + tid];
        float4 a1 = D2[rb + 256 + tid];
        float4 d0 = sqrt4(a0), d1 = sqrt4(a1);
        float4 rr0 = s_rr[tid], rr1 = s_rr[256 + tid];

        float dacc = rr0.x * d0.x + rr0.y * d0.y + rr0.z * d0.z + rr0.w * d0.w
                   + rr1.x * d1.x + rr1.y * d1.y + rr1.z * d1.z + rr1.w * d1.w;
        float cacc = 0.f, lacc = 0.f;
        if (rlors_prev != 0.0f) {
            float4 e0 = exp2f4(c0, a0);
            float4 e1 = exp2f4(c0, a1);
            float4 q0 = s_q[tid], q1 = s_q[256 + tid];
            float w;
            w = e0.x * q0.x; cacc += w * d0.x; lacc += w;
            w = e0.y * q0.y; cacc += w * d0.y; lacc += w;
            w = e0.z * q0.z; cacc += w * d0.z; lacc += w;
            w = e0.w * q0.w; cacc += w * d0.w; lacc += w;
            w = e1.x * q1.x; cacc += w * d1.x; lacc += w;
            w = e1.y * q1.y; cacc += w * d1.y; lacc += w;
            w = e1.z * q1.z; cacc += w * d1.z; lacc += w;
            w = e1.w * q1.w; cacc += w * d1.w; lacc += w;
        }
        float va = cacc, vb = lacc, vc = dacc;
#pragma unroll
        for (int o = 16; o > 0; o >>= 1) {
            va += __shfl_xor_sync(0xffffffffu, va, o);
            vb += __shfl_xor_sync(0xffffffffu, vb, o);
            vc += __shfl_xor_sync(0xffffffffu, vc, o);
        }
        float* red = s_redbuf + (pr & 1) * 24;
        if ((tid & 31) == 0) {
            int w = tid >> 5;
            red[w] = va; red[8 + w] = vb; red[16 + w] = vc;
        }
        __syncthreads();
        float Rc = 0.f, Rl = 0.f, Rd = 0.f;
#pragma unroll
        for (int k = 0; k < 8; k++) { Rc += red[k]; Rl += red[8 + k]; Rd += red[16 + k]; }
        pr++;

        if (tid == 0) {
            if (rlors_prev != 0.0f) {
                g_cost[gi] += rlors_prev * Rc;
                g_rl[gi] = fmaxf(g_rl[gi] - rlors_prev * Rl, 0.0f);
            }
            g_D[gi] = Rd;
        }
    }
}

/* Epilogue per batch:
 * S = sum rr; rlors0_i = rl_i/(S+1e-9); RLOR = sum rlors0;
 * level-0 q_j ~= rr_j * min(1/RLOR, 1)  (error <= 1e-9 mass per column)
 * out = sum cost_i + min(1/RLOR,1) * sum(rl_i * D_i) / (S+1e-9). */
__global__ void __launch_bounds__(TPB) k_epi(float* __restrict__ out) {
    __shared__ float red[32];
    int b = blockIdx.x, tid = threadIdx.x;
    float S = 0.f, C = 0.f, L = 0.f, LD = 0.f;
    for (int j = tid; j < MM; j += TPB) S += g_rr[b * MM + j];
    for (int i = tid; i < NN; i += TPB) {
        C += g_cost[b * NN + i];
        float rl = g_rl[b * NN + i];
        L += rl;
        LD += rl * g_D[b * NN + i];
    }
#pragma unroll
    for (int o = 16; o > 0; o >>= 1) {
        S  += __shfl_xor_sync(0xffffffffu, S, o);
        C  += __shfl_xor_sync(0xffffffffu, C, o);
        L  += __shfl_xor_sync(0xffffffffu, L, o);
        LD += __shfl_xor_sync(0xffffffffu, LD, o);
    }
    if ((tid & 31) == 0) {
        int w = tid >> 5;
        red[w] = S; red[8 + w] = C; red[16 + w] = L; red[24 + w] = LD;
    }
    __syncthreads();
    if (tid == 0) {
        float Sf = 0.f, Cf = 0.f, Lf = 0.f, LDf = 0.f;
#pragma unroll
        for (int k = 0; k < 8; k++) {
            Sf += red[k]; Cf += red[8 + k]; Lf += red[16 + k]; LDf += red[24 + k];
        }
        float Sden = Sf + 1e-9f;
        float RLOR = Lf / Sden;
        float kk = fminf(1.0f / RLOR, 1.0f);  /* RLOR==0 -> inf -> 1 */
        out[b] = Cf + kk * LDf / Sden;
    }
}

extern "C" void kernel_launch(void* const* d_in, const int* in_sizes, int n_in,
                              void* d_out, int out_size) {
    const float* xyz1 = (const float*)d_in[0];
    const float* xyz2 = (const float*)d_in[1];
    float* out = (float*)d_out;

    k_init<<<(BB * NN) / TPB, TPB>>>();
    k_prologue<<<dim3(NN / PRO_RPB, BB), TPB>>>(xyz1, xyz2);

    /* c[p] = level_p * log2(e), level_p = -0.25 * 4^p  (p = 8..0) */
    float c[9];
    for (int p = 0; p <= 8; p++)
        c[p] = (float)(-0.25 * pow(4.0, (double)p) * 1.4426950408889634);

    dim3 rg(PARTS, BB);
    /* Round p=8: A only */
    k_round<<<rg, TPB>>>(c[8], 0, 1);
    k_colB<<<(BB * MM) / TPB, TPB>>>();
    /* Fused C(p+1)+A(p) for p=7..0 */
    for (int p = 7; p >= 0; p--) {
        k_round<<<rg, TPB>>>(c[p], 1, 1);
        k_colB<<<(BB * MM) / TPB, TPB>>>();
    }
    /* C(0) fused with level-0 row sums */
    k_final<<<rg, TPB>>>(c[0]);
    k_epi<<<BB, TPB>>>(out);
}